// round 9
// baseline (speedup 1.0000x reference)
#include <cuda_runtime.h>
#include <cstdint>

// CropAndResize: image (8,256,200,200) f32 NCHW, boxes (512,4) [y1,x1,y2,x2],
// box_indices (512,) int32 -> out (512,256,14,14) f32. Bilinear, extrap 0.
//
// R9: intra-CTA load/gather pipeline. Half-plane loaded as 4 cp.async commit
// groups (row chunks); prep buckets (box,row) entries into 8 row segments per
// image; gather of segment s runs while chunks s+1.. stream from DRAM.

#define IH 200
#define IW 200
#define CROP 14
#define NCH 256
#define NBOX 512
#define NIMG 8
#define PLANE (IH * IW)
#define POS (CROP * CROP)          // 196
#define PITCH 204                  // smem row pitch (floats), 816B rows
#define MAXBI 128                  // max boxes per image
#define CAP (MAXBI * CROP)         // entry capacity per segment (worst case)
#define TPB 896                    // 64 entry-groups x 14 cols
#define EGRP (TPB / CROP)          // 64
#define CPR 50                     // 16B chunks per image row
#define NSEG 8                     // row segments per image (4 per half)

__device__ int   d_nbox[NIMG];
__device__ int   d_nent[NIMG * NSEG];
__device__ uint2 d_xtab[NIMG * MAXBI * CROP];   // {x0 | vx<<8, lx}
__device__ uint2 d_ent[NIMG * NSEG * CAP];      // {nid|slot<<9|o<<17|dy<<24|vy<<25|r<<26, ly}

__global__ __launch_bounds__(NBOX) void prep_kernel(
    const float* __restrict__ boxes,
    const int*   __restrict__ box_idx)
{
    const int n = threadIdx.x;
    if (n < NIMG) d_nbox[n] = 0;
    if (n < NIMG * NSEG) d_nent[n] = 0;
    __syncthreads();

    const int img  = box_idx[n];
    const int slot = atomicAdd(&d_nbox[img], 1);   // order irrelevant
    const float4 bq = ((const float4*)boxes)[n];   // y1,x1,y2,x2
    const float ys = (bq.z - bq.x) * (float)(IH - 1) * (1.0f / (CROP - 1));
    const float xs = (bq.w - bq.y) * (float)(IW - 1) * (1.0f / (CROP - 1));

    #pragma unroll
    for (int k = 0; k < CROP; ++k) {
        {   // x table (per box, per crop-col)
            const float v  = bq.y * (float)(IW - 1) + (float)k * xs;
            const float fl = floorf(v);
            const int x0 = (int)fminf(fmaxf(fl, 0.0f), (float)(IW - 1));
            const unsigned vx = (v >= 0.0f && v <= (float)(IW - 1)) ? 1u : 0u;
            d_xtab[(img * MAXBI + slot) * CROP + k] =
                make_uint2((unsigned)x0 | (vx << 8), __float_as_uint(v - fl));
        }
        {   // y row -> entry in owning row-segment's list
            const float v  = bq.x * (float)(IH - 1) + (float)k * ys;
            const float fl = floorf(v);
            const int y0 = (int)fminf(fmaxf(fl, 0.0f), (float)(IH - 1));
            const int h  = (y0 >= 100) ? 1 : 0;
            const int o  = y0 - 100 * h;                 // 0..99
            const int seg = h * 4 + o / 25;              // 0..7
            const unsigned dy = (y0 < IH - 1) ? 1u : 0u;
            const unsigned vy = (v >= 0.0f && v <= (float)(IH - 1)) ? 1u : 0u;
            const int idx = atomicAdd(&d_nent[img * NSEG + seg], 1);
            d_ent[(img * NSEG + seg) * CAP + idx] = make_uint2(
                (unsigned)n | ((unsigned)slot << 9) | ((unsigned)o << 17)
                | (dy << 24) | (vy << 25) | ((unsigned)k << 26),
                __float_as_uint(v - fl));
        }
    }
}

// Dynamic smem layout (bytes)
#define BUF_BYTES (101 * PITCH * 4)                  // 82416
#define SM_XTAB   BUF_BYTES                          // 14336
#define SM_ENT    (SM_XTAB + MAXBI * CROP * 8)       // 14336
#define SM_TOTAL  (SM_ENT + CAP * 8)                 // 111088 -> 2 CTAs/SM

__global__ __launch_bounds__(TPB, 2) void crop_resize_kernel(
    const float* __restrict__ image,
    float*       __restrict__ out)
{
    extern __shared__ char smem[];
    float* plane = (float*)smem;
    uint2* xtab  = (uint2*)(smem + SM_XTAB);
    uint2* ents  = (uint2*)(smem + SM_ENT);

    const int bx  = blockIdx.x;
    const int img = bx >> 9;
    const int ch  = (bx & 511) >> 1;
    const int h   = bx & 1;
    const int tid = threadIdx.x;

    // ---- Issue 4 row-chunk loads, one commit group each ----
    // half 0: rows 0..100 (101: row 100 is y1 partner), half 1: rows 100..199
    const int nrows = h ? 100 : 101;
    const char* srcb = (const char*)(image + ((size_t)img * NCH + ch) * PLANE
                                           + (size_t)(100 * h) * IW);
    const uint32_t smem_b = (uint32_t)__cvta_generic_to_shared(smem);
    const int cstart[5] = {0, 26, 51, 76, nrows};
    #pragma unroll
    for (int c = 0; c < 4; ++c) {
        const int r0  = cstart[c];
        const int n16 = (cstart[c + 1] - r0) * CPR;
        for (int i = tid; i < n16; i += TPB) {
            const int row = r0 + i / CPR;
            const int c16 = i - (row - r0) * CPR;
            asm volatile("cp.async.cg.shared.global [%0], [%1], 16;"
                         :: "r"(smem_b + row * (PITCH * 4) + c16 * 16),
                            "l"(srcb + row * (IW * 4) + c16 * 16));
        }
        asm volatile("cp.async.commit_group;");
    }

    // ---- Overlapped with in-flight loads: pads + table copies ----
    if (tid < 101) {   // zero row pads (x0=199 pair reads land here; lx=0)
        float4* pad = (float4*)(smem + tid * (PITCH * 4) + IW * 4);
        *pad = make_float4(0.f, 0.f, 0.f, 0.f);
    }

    const int nbs = d_nbox[img];
    for (int t = tid; t < nbs * CROP; t += TPB)
        xtab[t] = d_xtab[img * MAXBI * CROP + t];

    int scnt[4], soff[4];
    {
        int acc = 0;
        #pragma unroll
        for (int s = 0; s < 4; ++s) {
            scnt[s] = d_nent[img * NSEG + h * 4 + s];
            soff[s] = acc;
            acc += scnt[s];
        }
    }
    #pragma unroll
    for (int s = 0; s < 4; ++s) {
        const uint2* src = &d_ent[(img * NSEG + h * 4 + s) * CAP];
        for (int t = tid; t < scnt[s]; t += TPB)
            ents[soff[s] + t] = src[t];
    }

    // ---- Pipelined gather: seg s needs only chunks 0..s ----
    const int e0  = tid / CROP;          // 0..63
    const int col = tid - e0 * CROP;     // 0..13
    float* outb = out + (size_t)ch * POS + col;

    auto gather = [&](int off, int cnt) {
        for (int e = e0; e < cnt; e += EGRP) {
            const uint2 E = ents[off + e];
            const unsigned nid  = E.x & 511u;
            const unsigned slot = (E.x >> 9) & 255u;
            const int      o    = (E.x >> 17) & 127;
            const unsigned dy   = (E.x >> 24) & 1u;
            const unsigned vyr  = E.x >> 25;          // vy | r<<1
            const float    ly   = __uint_as_float(E.y);

            const uint2 tx = xtab[slot * CROP + col];
            const int   x0 = tx.x & 255;
            const float lx = __uint_as_float(tx.y);

            const float* r0 = plane + o * PITCH + x0;
            const float* r1 = r0 + dy * PITCH;
            const float tl = r0[0], tr = r0[1];
            const float bl = r1[0], br = r1[1];
            const float top = fmaf(tr - tl, lx, tl);
            const float bot = fmaf(br - bl, lx, bl);
            float val = fmaf(bot - top, ly, top);
            if (!(vyr & (tx.x >> 8) & 1u)) val = 0.0f;

            __stcs(outb + (size_t)nid * (NCH * POS) + (vyr >> 1) * CROP, val);
        }
    };

    asm volatile("cp.async.wait_group 3;");
    __syncthreads();
    gather(soff[0], scnt[0]);
    asm volatile("cp.async.wait_group 2;");
    __syncthreads();
    gather(soff[1], scnt[1]);
    asm volatile("cp.async.wait_group 1;");
    __syncthreads();
    gather(soff[2], scnt[2]);
    asm volatile("cp.async.wait_group 0;");
    __syncthreads();
    gather(soff[3], scnt[3]);
}

extern "C" void kernel_launch(void* const* d_in, const int* in_sizes, int n_in,
                              void* d_out, int out_size)
{
    const float* image   = (const float*)d_in[0];
    const float* boxes   = (const float*)d_in[1];
    const int*   box_idx = (const int*)d_in[2];
    float*       out     = (float*)d_out;

    static bool attr_set = false;
    if (!attr_set) {
        cudaFuncSetAttribute(crop_resize_kernel,
                             cudaFuncAttributeMaxDynamicSharedMemorySize,
                             SM_TOTAL);
        attr_set = true;
    }

    prep_kernel<<<1, NBOX>>>(boxes, box_idx);
    crop_resize_kernel<<<NIMG * NCH * 2, TPB, SM_TOTAL>>>(image, out);
}

// round 10
// speedup vs baseline: 1.4013x; 1.4013x over previous
#include <cuda_runtime.h>

// CropAndResize: image (8,256,200,200) f32 NCHW, boxes (512,4) [y1,x1,y2,x2],
// box_indices (512,) int32 -> out (512,256,14,14) f32. Bilinear, extrap 0.
//
// R10: direct-gather (R3 skeleton: sorted boxes, cchunk-major blocks, fixed
// position per thread-pair) with LANE-PAIRED corner loads: lanes 2k/2k+1 load
// x0/x1 of the same sample in one instruction (halves L1tex wavefronts),
// recombine via shfl_xor.

#define IH 200
#define IW 200
#define CROP 14
#define NCH 256
#define NBOX 512
#define NIMG 8
#define PLANE (IH * IW)
#define POS (CROP * CROP)          // 196
#define CCHUNK 64                  // channels per block
#define NCHUNKS (NCH / CCHUNK)     // 4
#define TPB 416                    // 13 warps; 208 pairs (196 live)

__device__ int d_perm[NBOX];       // box ids sorted by image index

__global__ __launch_bounds__(NBOX) void sort_boxes_kernel(
    const int* __restrict__ box_idx)
{
    __shared__ int cnt[NIMG];
    __shared__ int off[NIMG + 1];
    const int tid = threadIdx.x;
    if (tid < NIMG) cnt[tid] = 0;
    __syncthreads();
    const int b = box_idx[tid];
    atomicAdd(&cnt[b], 1);
    __syncthreads();
    if (tid == 0) {
        int s = 0;
        for (int i = 0; i < NIMG; ++i) { off[i] = s; s += cnt[i]; }
        off[NIMG] = s;
    }
    __syncthreads();
    const int pos = atomicAdd(&off[b], 1);   // bucket-internal order irrelevant
    d_perm[pos] = tid;
}

__global__ __launch_bounds__(TPB) void crop_resize_kernel(
    const float* __restrict__ image,
    const float* __restrict__ boxes,
    const int*   __restrict__ box_idx,
    float*       __restrict__ out)
{
    __shared__ int   sy0[CROP], sy1[CROP], sx0[CROP], sx1[CROP];
    __shared__ float sly[CROP], slx[CROP];
    __shared__ unsigned svy[CROP], svx[CROP];
    __shared__ int sn;
    __shared__ const float* splane;

    const int cchunk = blockIdx.x / NBOX;   // cchunk-major: concurrent blocks
    const int spos   = blockIdx.x % NBOX;   // share a chunk, grouped by image
    const int tid    = threadIdx.x;

    if (tid == 0) {
        const int n = d_perm[spos];
        sn = n;
        splane = image + (size_t)box_idx[n] * NCH * PLANE;
    }
    __syncthreads();
    const int n = sn;

    // Per-box interpolation coefficients: threads 0..13 x-axis, 14..27 y-axis.
    if (tid < 2 * CROP) {
        const bool isx = (tid < CROP);
        const int  k   = isx ? tid : tid - CROP;
        const float a1 = boxes[n * 4 + (isx ? 1 : 0)];
        const float a2 = boxes[n * 4 + (isx ? 3 : 2)];
        const float D  = isx ? (float)(IW - 1) : (float)(IH - 1);
        const float scale = (a2 - a1) * D * (1.0f / (CROP - 1));
        const float v  = a1 * D + (float)k * scale;
        const unsigned valid = (v >= 0.0f) && (v <= D);
        const float fl = floorf(v);
        const float ce = ceilf(v);
        const float l  = v - fl;
        const int i0 = (int)fminf(fmaxf(fl, 0.0f), D);
        const int i1 = (int)fminf(fmaxf(ce, 0.0f), D);
        if (isx) { sx0[k] = i0; sx1[k] = i1; slx[k] = l; svx[k] = valid; }
        else     { sy0[k] = i0; sy1[k] = i1; sly[k] = l; svy[k] = valid; }
    }
    __syncthreads();

    // Pair decode: pair owns one crop position; lane parity = which x corner.
    const int pair = tid >> 1;
    const int q    = tid & 1;
    const bool active = pair < POS;
    const int pos  = active ? pair : POS - 1;   // dummy pairs compute, don't store
    const int r    = pos / CROP;
    const int col  = pos - r * CROP;

    const int y0 = sy0[r], y1 = sy1[r];
    const float lx = slx[col], ly = sly[r];
    const bool valid = (svy[r] & svx[col]) != 0;
    const int xm = q ? sx1[col] : sx0[col];     // my corner's x
    const int oT = y0 * IW + xm;
    const int oB = y1 * IW + xm;
    const bool doStore = active && (q == 0);

    const float* pl = splane + (size_t)cchunk * CCHUNK * PLANE;
    float* outp = out + (size_t)n * NCH * POS + (size_t)cchunk * CCHUNK * POS + pos;

    #pragma unroll 4
    for (int c = 0; c < CCHUNK; ++c) {
        const float vt = __ldg(pl + oT);        // one instr covers x0 AND x1
        const float vb = __ldg(pl + oB);        // of 16 samples -> few lines
        const float ot = __shfl_xor_sync(0xFFFFFFFFu, vt, 1);
        const float ob = __shfl_xor_sync(0xFFFFFFFFu, vb, 1);
        const float tl = q ? ot : vt;
        const float tr = q ? vt : ot;
        const float bl = q ? ob : vb;
        const float br = q ? vb : ob;
        const float top = fmaf(tr - tl, lx, tl);
        const float bot = fmaf(br - bl, lx, bl);
        float val = fmaf(bot - top, ly, top);
        if (!valid) val = 0.0f;
        if (doStore) __stcs(outp, val);
        pl   += PLANE;
        outp += POS;
    }
}

extern "C" void kernel_launch(void* const* d_in, const int* in_sizes, int n_in,
                              void* d_out, int out_size)
{
    const float* image   = (const float*)d_in[0];
    const float* boxes   = (const float*)d_in[1];
    const int*   box_idx = (const int*)d_in[2];
    float*       out     = (float*)d_out;

    sort_boxes_kernel<<<1, NBOX>>>(box_idx);
    crop_resize_kernel<<<NCHUNKS * NBOX, TPB>>>(image, boxes, box_idx, out);
}